// round 3
// baseline (speedup 1.0000x reference)
#include <cuda_runtime.h>
#include <math.h>

#define Bn 32
#define Ln 4096
#define Cn 256
#define Vn 5
#define Tn 3
#define EPSf 1e-8f
#define LNEPS 1e-5f
#define NCHUNK 16

// ---- scratch (no allocations allowed; __device__ globals) ----
__device__ __align__(16) float g_basep[NCHUNK][Bn * Cn];  // per-chunk partial sums over L
__device__ __align__(16) float g_slots[Bn * Vn * Cn];
__device__ __align__(16) float g_kq[Bn * Vn * Cn];     // scale * Wq @ k  (per slot row)
__device__ __align__(16) float g_y[Bn * Vn * Cn];      // sum_l attn * x_norm
__device__ __align__(16) float g_asum[Bn * Vn];        // sum_l attn
__device__ __align__(16) float g_M[Cn * Cn];           // M[cj][ci] = scale * sum_co Wk[cj,co]*Wq[ci,co]

// ------------------------------------------------------------------
// helpers
// ------------------------------------------------------------------
__device__ __forceinline__ void blockReduce2(float& s, float& q, volatile float* red) {
    int lane = threadIdx.x & 31, wid = threadIdx.x >> 5;
#pragma unroll
    for (int o = 16; o; o >>= 1) {
        s += __shfl_xor_sync(0xFFFFFFFFu, s, o);
        q += __shfl_xor_sync(0xFFFFFFFFu, q, o);
    }
    if (lane == 0) { red[wid] = s; red[8 + wid] = q; }
    __syncthreads();
    s = red[0]; q = red[8];
#pragma unroll
    for (int i = 1; i < 8; i++) { s += red[i]; q += red[8 + i]; }
    __syncthreads();
}

// out[col] = sum_i sh[i] * W[i*ld + col]   (coalesced across threads = col)
__device__ __forceinline__ float gemv_col(const float* __restrict__ W, const float* sh,
                                          int n, int col, int ld) {
    float a0 = 0.f, a1 = 0.f, a2 = 0.f, a3 = 0.f;
#pragma unroll 2
    for (int i = 0; i < n; i += 4) {
        a0 = fmaf(sh[i + 0], W[(size_t)(i + 0) * ld + col], a0);
        a1 = fmaf(sh[i + 1], W[(size_t)(i + 1) * ld + col], a1);
        a2 = fmaf(sh[i + 2], W[(size_t)(i + 2) * ld + col], a2);
        a3 = fmaf(sh[i + 3], W[(size_t)(i + 3) * ld + col], a3);
    }
    return (a0 + a1) + (a2 + a3);
}

// LN(slot row) @ M -> g_kq[row]   (called with full 256-thread block; sh has Cn floats)
__device__ __forceinline__ void slots_to_kq(int r, float slotval,
                                            const float* __restrict__ gs,
                                            const float* __restrict__ bs,
                                            float* sh, volatile float* red) {
    int tid = threadIdx.x;
    float s = slotval, q = slotval * slotval;
    blockReduce2(s, q, red);
    float mean = s * (1.0f / Cn);
    float rs = rsqrtf(q * (1.0f / Cn) - mean * mean + LNEPS);
    sh[tid] = (slotval - mean) * rs * gs[tid] + bs[tid];
    __syncthreads();
    g_kq[(size_t)r * Cn + tid] = gemv_col(g_M, sh, Cn, tid, Cn);
}

// ------------------------------------------------------------------
// kernels
// ------------------------------------------------------------------
__global__ void zero_buffers() {
    int i = blockIdx.x * 256 + threadIdx.x;
    if (i < Bn * Vn * Cn) g_y[i] = 0.f;
    if (i < Bn * Vn)      g_asum[i] = 0.f;
}

__global__ void base_reduce(const float* __restrict__ f) {
    int b = blockIdx.y, chunk = blockIdx.x, c = threadIdx.x;
    const int RPC = Ln / NCHUNK;  // 256 rows per block
    size_t base = ((size_t)b * Ln + (size_t)chunk * RPC) * Cn + c;
    float s = 0.f;
#pragma unroll 4
    for (int i = 0; i < RPC; i++) s += f[base + (size_t)i * Cn];
    g_basep[chunk][b * Cn + c] = s;
}

__global__ void compute_M(const float* __restrict__ Wk, const float* __restrict__ Wq,
                          const float* __restrict__ scale_p) {
    __shared__ float4 wk4[Cn / 4];
    int cj = blockIdx.x, ci = threadIdx.x;
    if (threadIdx.x < 64) wk4[threadIdx.x] = ((const float4*)Wk)[(size_t)cj * 64 + threadIdx.x];
    __syncthreads();
    const float4* wq4 = (const float4*)Wq + (size_t)ci * 64;
    float a0 = 0, a1 = 0, a2 = 0, a3 = 0;
#pragma unroll 8
    for (int qx = 0; qx < 64; qx++) {
        float4 wv = wq4[qx]; float4 kv = wk4[qx];
        a0 = fmaf(kv.x, wv.x, a0); a1 = fmaf(kv.y, wv.y, a1);
        a2 = fmaf(kv.z, wv.z, a2); a3 = fmaf(kv.w, wv.w, a3);
    }
    g_M[(size_t)cj * Cn + ci] = scale_p[0] * ((a0 + a1) + (a2 + a3));
}

__global__ void init_slots(const float* __restrict__ noise, const float* __restrict__ ns_p) {
    int r = blockIdx.x, c = threadIdx.x, b = r / Vn;
    float s = 0.f;
#pragma unroll
    for (int k = 0; k < NCHUNK; k++) s += g_basep[k][b * Cn + c];
    g_slots[(size_t)r * Cn + c] =
        s * (1.0f / Ln) + noise[(size_t)r * Cn + c] * fabsf(ns_p[0]);
}

__global__ void prep_kq(const float* __restrict__ gs, const float* __restrict__ bs) {
    __shared__ float sh[Cn];
    __shared__ float red[16];
    int r = blockIdx.x;
    slots_to_kq(r, g_slots[(size_t)r * Cn + threadIdx.x], gs, bs, sh, red);
}

// ---- main streaming pass: per token LN + logits + softmax + y accumulation ----
__global__ void __launch_bounds__(256)
main_pass(const float* __restrict__ feat, const float* __restrict__ gin,
          const float* __restrict__ bin, float* __restrict__ attn_out, int write_attn) {
    __shared__ float4 kq4[Vn][64];
    __shared__ float4 gi4[64], bi4[64];
    __shared__ float ysh[Vn][Cn];
    __shared__ float asum_sh[Vn];

    int b = blockIdx.y;
    int tid = threadIdx.x, lane = tid & 31, wid = tid >> 5;

    for (int i = tid; i < Vn * 64; i += 256)
        kq4[i / 64][i % 64] = ((const float4*)g_kq)[(size_t)b * Vn * 64 + i];
    if (tid < 64) { gi4[tid] = ((const float4*)gin)[tid]; bi4[tid] = ((const float4*)bin)[tid]; }
    for (int i = tid; i < Vn * Cn; i += 256) ((float*)ysh)[i] = 0.f;
    if (tid < Vn) asum_sh[tid] = 0.f;
    __syncthreads();

    float4 y0[Vn], y1[Vn];
    float as[Vn];
#pragma unroll
    for (int v = 0; v < Vn; v++) {
        y0[v] = make_float4(0.f, 0.f, 0.f, 0.f);
        y1[v] = make_float4(0.f, 0.f, 0.f, 0.f);
        as[v] = 0.f;
    }
    float4 gv0 = gi4[lane], gv1 = gi4[32 + lane];
    float4 bv0 = bi4[lane], bv1 = bi4[32 + lane];

    int l0 = blockIdx.x * 128 + wid * 16;
    for (int i = 0; i < 16; i++) {
        int l = l0 + i;
        const float4* fr = (const float4*)feat + ((size_t)b * Ln + l) * 64;
        float4 f0 = fr[lane], f1 = fr[32 + lane];

        float s = (f0.x + f0.y) + (f0.z + f0.w) + (f1.x + f1.y) + (f1.z + f1.w);
        float q = fmaf(f0.x, f0.x, fmaf(f0.y, f0.y, fmaf(f0.z, f0.z, f0.w * f0.w))) +
                  fmaf(f1.x, f1.x, fmaf(f1.y, f1.y, fmaf(f1.z, f1.z, f1.w * f1.w)));
#pragma unroll
        for (int o = 16; o; o >>= 1) {
            s += __shfl_xor_sync(0xFFFFFFFFu, s, o);
            q += __shfl_xor_sync(0xFFFFFFFFu, q, o);
        }
        float mean = s * (1.0f / Cn);
        float rs = rsqrtf(q * (1.0f / Cn) - mean * mean + LNEPS);

        float4 x0, x1;
        x0.x = fmaf((f0.x - mean) * rs, gv0.x, bv0.x);
        x0.y = fmaf((f0.y - mean) * rs, gv0.y, bv0.y);
        x0.z = fmaf((f0.z - mean) * rs, gv0.z, bv0.z);
        x0.w = fmaf((f0.w - mean) * rs, gv0.w, bv0.w);
        x1.x = fmaf((f1.x - mean) * rs, gv1.x, bv1.x);
        x1.y = fmaf((f1.y - mean) * rs, gv1.y, bv1.y);
        x1.z = fmaf((f1.z - mean) * rs, gv1.z, bv1.z);
        x1.w = fmaf((f1.w - mean) * rs, gv1.w, bv1.w);

        float lg[Vn];
#pragma unroll
        for (int v = 0; v < Vn; v++) {
            float4 kA = kq4[v][lane], kB = kq4[v][32 + lane];
            float t = x0.x * kA.x;
            t = fmaf(x0.y, kA.y, t); t = fmaf(x0.z, kA.z, t); t = fmaf(x0.w, kA.w, t);
            t = fmaf(x1.x, kB.x, t); t = fmaf(x1.y, kB.y, t);
            t = fmaf(x1.z, kB.z, t); t = fmaf(x1.w, kB.w, t);
#pragma unroll
            for (int o = 16; o; o >>= 1) t += __shfl_xor_sync(0xFFFFFFFFu, t, o);
            lg[v] = t;
        }
        float mx = lg[0];
#pragma unroll
        for (int v = 1; v < Vn; v++) mx = fmaxf(mx, lg[v]);
        float e[Vn], se = 0.f;
#pragma unroll
        for (int v = 0; v < Vn; v++) { e[v] = __expf(lg[v] - mx); se += e[v]; }
        float inv = 1.0f / se;
#pragma unroll
        for (int v = 0; v < Vn; v++) {
            float a = e[v] * inv;
            e[v] = a;
            as[v] += a;
            y0[v].x = fmaf(a, x0.x, y0[v].x); y0[v].y = fmaf(a, x0.y, y0[v].y);
            y0[v].z = fmaf(a, x0.z, y0[v].z); y0[v].w = fmaf(a, x0.w, y0[v].w);
            y1[v].x = fmaf(a, x1.x, y1[v].x); y1[v].y = fmaf(a, x1.y, y1[v].y);
            y1[v].z = fmaf(a, x1.z, y1[v].z); y1[v].w = fmaf(a, x1.w, y1[v].w);
        }
        if (write_attn && lane < Vn) {
            float av = e[0];
            if (lane == 1) av = e[1];
            else if (lane == 2) av = e[2];
            else if (lane == 3) av = e[3];
            else if (lane == 4) av = e[4];
            attn_out[((size_t)b * Ln + l) * Vn + lane] = av;
        }
    }

    // warp partials -> block smem
#pragma unroll
    for (int v = 0; v < Vn; v++) {
        atomicAdd(&ysh[v][4 * lane + 0], y0[v].x);
        atomicAdd(&ysh[v][4 * lane + 1], y0[v].y);
        atomicAdd(&ysh[v][4 * lane + 2], y0[v].z);
        atomicAdd(&ysh[v][4 * lane + 3], y0[v].w);
        atomicAdd(&ysh[v][128 + 4 * lane + 0], y1[v].x);
        atomicAdd(&ysh[v][128 + 4 * lane + 1], y1[v].y);
        atomicAdd(&ysh[v][128 + 4 * lane + 2], y1[v].z);
        atomicAdd(&ysh[v][128 + 4 * lane + 3], y1[v].w);
    }
    if (lane == 0) {
#pragma unroll
        for (int v = 0; v < Vn; v++) atomicAdd(&asum_sh[v], as[v]);
    }
    __syncthreads();
#pragma unroll
    for (int v = 0; v < Vn; v++)
        atomicAdd(&g_y[((size_t)b * Vn + v) * Cn + tid], ysh[v][tid]);
    if (tid < Vn) atomicAdd(&g_asum[b * Vn + tid], asum_sh[tid]);
}

// ---- per-slot chain: updates = (y@Wv)/asum, LN, MLP, slots+=, (LN, @M -> kq) ----
__global__ void chain_kernel(const float* __restrict__ Wv,
                             const float* __restrict__ gu, const float* __restrict__ bu,
                             const float* __restrict__ W1, const float* __restrict__ b1,
                             const float* __restrict__ W2, const float* __restrict__ b2,
                             const float* __restrict__ gs, const float* __restrict__ bs,
                             float* __restrict__ slots_out, int last) {
    __shared__ float shA[2 * Cn];
    __shared__ float shB[Cn];
    __shared__ float red[16];
    __shared__ float asum_s;
    int r = blockIdx.x, tid = threadIdx.x;

    shB[tid] = g_y[(size_t)r * Cn + tid];
    if (tid == 0) asum_s = g_asum[r] + EPSf;
    __syncthreads();
    // zero accumulators for next iteration (this block owns row r exclusively)
    g_y[(size_t)r * Cn + tid] = 0.f;
    if (tid == 0) g_asum[r] = 0.f;

    float u = gemv_col(Wv, shB, Cn, tid, Cn) / asum_s;

    float s = u, q = u * u;
    blockReduce2(s, q, red);  // internal syncs also fence shB reads
    float mean = s * (1.0f / Cn);
    float rs = rsqrtf(q * (1.0f / Cn) - mean * mean + LNEPS);
    float h = (u - mean) * rs * gu[tid] + bu[tid];
    shB[tid] = h;
    __syncthreads();

    float m0 = gemv_col(W1, shB, Cn, tid, 2 * Cn) + b1[tid];
    float m1 = gemv_col(W1, shB, Cn, tid + Cn, 2 * Cn) + b1[tid + Cn];
    shA[tid] = fmaxf(m0, 0.f);
    shA[tid + Cn] = fmaxf(m1, 0.f);
    __syncthreads();

    float d = gemv_col(W2, shA, 2 * Cn, tid, Cn) + b2[tid];
    float ns = g_slots[(size_t)r * Cn + tid] + d;
    g_slots[(size_t)r * Cn + tid] = ns;
    if (last) {
        slots_out[(size_t)r * Cn + tid] = ns;
        return;
    }
    slots_to_kq(r, ns, gs, bs, shB, red);
}

// ------------------------------------------------------------------
extern "C" void kernel_launch(void* const* d_in, const int* in_sizes, int n_in,
                              void* d_out, int out_size) {
    (void)in_sizes; (void)n_in; (void)out_size;
    const float* feat  = (const float*)d_in[0];
    const float* noise = (const float*)d_in[1];
    const float* Wq    = (const float*)d_in[2];
    const float* Wk    = (const float*)d_in[3];
    const float* Wv    = (const float*)d_in[4];
    const float* scale = (const float*)d_in[5];
    const float* gin   = (const float*)d_in[6];
    const float* bin   = (const float*)d_in[7];
    const float* gs    = (const float*)d_in[8];
    const float* bs    = (const float*)d_in[9];
    const float* gu    = (const float*)d_in[10];
    const float* bu    = (const float*)d_in[11];
    const float* W1    = (const float*)d_in[12];
    const float* b1    = (const float*)d_in[13];
    const float* W2    = (const float*)d_in[14];
    const float* b2    = (const float*)d_in[15];
    const float* nsc   = (const float*)d_in[16];

    float* out = (float*)d_out;
    float* slots_out = out;                   // [B,V,C] first
    float* attn_out = out + Bn * Vn * Cn;     // [B,L,V] second

    zero_buffers<<<160, 256>>>();
    base_reduce<<<dim3(NCHUNK, Bn), 256>>>(feat);
    compute_M<<<Cn, Cn>>>(Wk, Wq, scale);
    init_slots<<<Bn * Vn, Cn>>>(noise, nsc);
    prep_kq<<<Bn * Vn, Cn>>>(gs, bs);
    for (int t = 0; t < Tn; t++) {
        main_pass<<<dim3(Ln / 128, Bn), 256>>>(feat, gin, bin, attn_out, t == Tn - 1);
        chain_kernel<<<Bn * Vn, Cn>>>(Wv, gu, bu, W1, b1, W2, b2, gs, bs,
                                      slots_out, t == Tn - 1);
    }
}

// round 4
// speedup vs baseline: 1.0026x; 1.0026x over previous
#include <cuda_runtime.h>
#include <math.h>

#define Bn 32
#define Ln 4096
#define Cn 256
#define Vn 5
#define Tn 3
#define EPSf 1e-8f
#define LNEPS 1e-5f
#define NCHUNK 16

// ---- scratch (no allocations allowed; __device__ globals) ----
__device__ __align__(16) float g_basep[NCHUNK][Bn * Cn];  // per-chunk partial sums over L
__device__ __align__(16) float g_slots[Bn * Vn * Cn];
__device__ __align__(16) float g_kq[Bn * Vn * Cn];     // scale * Wq @ k  (per slot row)
__device__ __align__(16) float g_y[Bn * Vn * Cn];      // sum_l attn * x_norm
__device__ __align__(16) float g_asum[Bn * Vn];        // sum_l attn
__device__ __align__(16) float g_M[Cn * Cn];           // M[cj][ci] = scale * sum_co Wk[cj,co]*Wq[ci,co]

// ------------------------------------------------------------------
// helpers
// ------------------------------------------------------------------
__device__ __forceinline__ void blockReduce2(float& s, float& q, volatile float* red) {
    int lane = threadIdx.x & 31, wid = threadIdx.x >> 5;
#pragma unroll
    for (int o = 16; o; o >>= 1) {
        s += __shfl_xor_sync(0xFFFFFFFFu, s, o);
        q += __shfl_xor_sync(0xFFFFFFFFu, q, o);
    }
    if (lane == 0) { red[wid] = s; red[8 + wid] = q; }
    __syncthreads();
    s = red[0]; q = red[8];
#pragma unroll
    for (int i = 1; i < 8; i++) { s += red[i]; q += red[8 + i]; }
    __syncthreads();
}

// out[col] = sum_i sh[i] * W[i*ld + col]   (coalesced across threads = col)
__device__ __forceinline__ float gemv_col(const float* __restrict__ W, const float* sh,
                                          int n, int col, int ld) {
    float a0 = 0.f, a1 = 0.f, a2 = 0.f, a3 = 0.f;
#pragma unroll 2
    for (int i = 0; i < n; i += 4) {
        a0 = fmaf(sh[i + 0], W[(size_t)(i + 0) * ld + col], a0);
        a1 = fmaf(sh[i + 1], W[(size_t)(i + 1) * ld + col], a1);
        a2 = fmaf(sh[i + 2], W[(size_t)(i + 2) * ld + col], a2);
        a3 = fmaf(sh[i + 3], W[(size_t)(i + 3) * ld + col], a3);
    }
    return (a0 + a1) + (a2 + a3);
}

// LN(slot row) @ M -> g_kq[row]   (called with full 256-thread block; sh has Cn floats)
__device__ __forceinline__ void slots_to_kq(int r, float slotval,
                                            const float* __restrict__ gs,
                                            const float* __restrict__ bs,
                                            float* sh, volatile float* red) {
    int tid = threadIdx.x;
    float s = slotval, q = slotval * slotval;
    blockReduce2(s, q, red);
    float mean = s * (1.0f / Cn);
    float rs = rsqrtf(q * (1.0f / Cn) - mean * mean + LNEPS);
    sh[tid] = (slotval - mean) * rs * gs[tid] + bs[tid];
    __syncthreads();
    g_kq[(size_t)r * Cn + tid] = gemv_col(g_M, sh, Cn, tid, Cn);
}

// ------------------------------------------------------------------
// kernels
// ------------------------------------------------------------------
__global__ void zero_buffers() {
    int i = blockIdx.x * 256 + threadIdx.x;
    if (i < Bn * Vn * Cn) g_y[i] = 0.f;
    if (i < Bn * Vn)      g_asum[i] = 0.f;
}

__global__ void base_reduce(const float* __restrict__ f) {
    int b = blockIdx.y, chunk = blockIdx.x, c = threadIdx.x;
    const int RPC = Ln / NCHUNK;  // 256 rows per block
    size_t base = ((size_t)b * Ln + (size_t)chunk * RPC) * Cn + c;
    float s = 0.f;
#pragma unroll 4
    for (int i = 0; i < RPC; i++) s += f[base + (size_t)i * Cn];
    g_basep[chunk][b * Cn + c] = s;
}

__global__ void compute_M(const float* __restrict__ Wk, const float* __restrict__ Wq,
                          const float* __restrict__ scale_p) {
    __shared__ float4 wk4[Cn / 4];
    int cj = blockIdx.x, ci = threadIdx.x;
    if (threadIdx.x < 64) wk4[threadIdx.x] = ((const float4*)Wk)[(size_t)cj * 64 + threadIdx.x];
    __syncthreads();
    const float4* wq4 = (const float4*)Wq + (size_t)ci * 64;
    float a0 = 0, a1 = 0, a2 = 0, a3 = 0;
#pragma unroll 8
    for (int qx = 0; qx < 64; qx++) {
        float4 wv = wq4[qx]; float4 kv = wk4[qx];
        a0 = fmaf(kv.x, wv.x, a0); a1 = fmaf(kv.y, wv.y, a1);
        a2 = fmaf(kv.z, wv.z, a2); a3 = fmaf(kv.w, wv.w, a3);
    }
    g_M[(size_t)cj * Cn + ci] = scale_p[0] * ((a0 + a1) + (a2 + a3));
}

__global__ void init_slots(const float* __restrict__ noise, const float* __restrict__ ns_p) {
    int r = blockIdx.x, c = threadIdx.x, b = r / Vn;
    float s = 0.f;
#pragma unroll
    for (int k = 0; k < NCHUNK; k++) s += g_basep[k][b * Cn + c];
    g_slots[(size_t)r * Cn + c] =
        s * (1.0f / Ln) + noise[(size_t)r * Cn + c] * fabsf(ns_p[0]);
}

__global__ void prep_kq(const float* __restrict__ gs, const float* __restrict__ bs) {
    __shared__ float sh[Cn];
    __shared__ float red[16];
    int r = blockIdx.x;
    slots_to_kq(r, g_slots[(size_t)r * Cn + threadIdx.x], gs, bs, sh, red);
}

// ---- main streaming pass: per token LN + logits + softmax + y accumulation ----
__global__ void __launch_bounds__(256)
main_pass(const float* __restrict__ feat, const float* __restrict__ gin,
          const float* __restrict__ bin, float* __restrict__ attn_out, int write_attn) {
    __shared__ float4 kq4[Vn][64];
    __shared__ float4 gi4[64], bi4[64];
    __shared__ float ysh[Vn][Cn];
    __shared__ float asum_sh[Vn];

    int b = blockIdx.y;
    int tid = threadIdx.x, lane = tid & 31, wid = tid >> 5;

    for (int i = tid; i < Vn * 64; i += 256)
        kq4[i / 64][i % 64] = ((const float4*)g_kq)[(size_t)b * Vn * 64 + i];
    if (tid < 64) { gi4[tid] = ((const float4*)gin)[tid]; bi4[tid] = ((const float4*)bin)[tid]; }
    for (int i = tid; i < Vn * Cn; i += 256) ((float*)ysh)[i] = 0.f;
    if (tid < Vn) asum_sh[tid] = 0.f;
    __syncthreads();

    float4 y0[Vn], y1[Vn];
    float as[Vn];
#pragma unroll
    for (int v = 0; v < Vn; v++) {
        y0[v] = make_float4(0.f, 0.f, 0.f, 0.f);
        y1[v] = make_float4(0.f, 0.f, 0.f, 0.f);
        as[v] = 0.f;
    }
    float4 gv0 = gi4[lane], gv1 = gi4[32 + lane];
    float4 bv0 = bi4[lane], bv1 = bi4[32 + lane];

    int l0 = blockIdx.x * 128 + wid * 16;
    for (int i = 0; i < 16; i++) {
        int l = l0 + i;
        const float4* fr = (const float4*)feat + ((size_t)b * Ln + l) * 64;
        float4 f0 = fr[lane], f1 = fr[32 + lane];

        float s = (f0.x + f0.y) + (f0.z + f0.w) + (f1.x + f1.y) + (f1.z + f1.w);
        float q = fmaf(f0.x, f0.x, fmaf(f0.y, f0.y, fmaf(f0.z, f0.z, f0.w * f0.w))) +
                  fmaf(f1.x, f1.x, fmaf(f1.y, f1.y, fmaf(f1.z, f1.z, f1.w * f1.w)));
#pragma unroll
        for (int o = 16; o; o >>= 1) {
            s += __shfl_xor_sync(0xFFFFFFFFu, s, o);
            q += __shfl_xor_sync(0xFFFFFFFFu, q, o);
        }
        float mean = s * (1.0f / Cn);
        float rs = rsqrtf(q * (1.0f / Cn) - mean * mean + LNEPS);

        float4 x0, x1;
        x0.x = fmaf((f0.x - mean) * rs, gv0.x, bv0.x);
        x0.y = fmaf((f0.y - mean) * rs, gv0.y, bv0.y);
        x0.z = fmaf((f0.z - mean) * rs, gv0.z, bv0.z);
        x0.w = fmaf((f0.w - mean) * rs, gv0.w, bv0.w);
        x1.x = fmaf((f1.x - mean) * rs, gv1.x, bv1.x);
        x1.y = fmaf((f1.y - mean) * rs, gv1.y, bv1.y);
        x1.z = fmaf((f1.z - mean) * rs, gv1.z, bv1.z);
        x1.w = fmaf((f1.w - mean) * rs, gv1.w, bv1.w);

        float lg[Vn];
#pragma unroll
        for (int v = 0; v < Vn; v++) {
            float4 kA = kq4[v][lane], kB = kq4[v][32 + lane];
            float t = x0.x * kA.x;
            t = fmaf(x0.y, kA.y, t); t = fmaf(x0.z, kA.z, t); t = fmaf(x0.w, kA.w, t);
            t = fmaf(x1.x, kB.x, t); t = fmaf(x1.y, kB.y, t);
            t = fmaf(x1.z, kB.z, t); t = fmaf(x1.w, kB.w, t);
#pragma unroll
            for (int o = 16; o; o >>= 1) t += __shfl_xor_sync(0xFFFFFFFFu, t, o);
            lg[v] = t;
        }
        float mx = lg[0];
#pragma unroll
        for (int v = 1; v < Vn; v++) mx = fmaxf(mx, lg[v]);
        float e[Vn], se = 0.f;
#pragma unroll
        for (int v = 0; v < Vn; v++) { e[v] = __expf(lg[v] - mx); se += e[v]; }
        float inv = 1.0f / se;
#pragma unroll
        for (int v = 0; v < Vn; v++) {
            float a = e[v] * inv;
            e[v] = a;
            as[v] += a;
            y0[v].x = fmaf(a, x0.x, y0[v].x); y0[v].y = fmaf(a, x0.y, y0[v].y);
            y0[v].z = fmaf(a, x0.z, y0[v].z); y0[v].w = fmaf(a, x0.w, y0[v].w);
            y1[v].x = fmaf(a, x1.x, y1[v].x); y1[v].y = fmaf(a, x1.y, y1[v].y);
            y1[v].z = fmaf(a, x1.z, y1[v].z); y1[v].w = fmaf(a, x1.w, y1[v].w);
        }
        if (write_attn && lane < Vn) {
            float av = e[0];
            if (lane == 1) av = e[1];
            else if (lane == 2) av = e[2];
            else if (lane == 3) av = e[3];
            else if (lane == 4) av = e[4];
            attn_out[((size_t)b * Ln + l) * Vn + lane] = av;
        }
    }

    // warp partials -> block smem
#pragma unroll
    for (int v = 0; v < Vn; v++) {
        atomicAdd(&ysh[v][4 * lane + 0], y0[v].x);
        atomicAdd(&ysh[v][4 * lane + 1], y0[v].y);
        atomicAdd(&ysh[v][4 * lane + 2], y0[v].z);
        atomicAdd(&ysh[v][4 * lane + 3], y0[v].w);
        atomicAdd(&ysh[v][128 + 4 * lane + 0], y1[v].x);
        atomicAdd(&ysh[v][128 + 4 * lane + 1], y1[v].y);
        atomicAdd(&ysh[v][128 + 4 * lane + 2], y1[v].z);
        atomicAdd(&ysh[v][128 + 4 * lane + 3], y1[v].w);
    }
    if (lane == 0) {
#pragma unroll
        for (int v = 0; v < Vn; v++) atomicAdd(&asum_sh[v], as[v]);
    }
    __syncthreads();
#pragma unroll
    for (int v = 0; v < Vn; v++)
        atomicAdd(&g_y[((size_t)b * Vn + v) * Cn + tid], ysh[v][tid]);
    if (tid < Vn) atomicAdd(&g_asum[b * Vn + tid], asum_sh[tid]);
}

// ---- per-slot chain: updates = (y@Wv)/asum, LN, MLP, slots+=, (LN, @M -> kq) ----
__global__ void chain_kernel(const float* __restrict__ Wv,
                             const float* __restrict__ gu, const float* __restrict__ bu,
                             const float* __restrict__ W1, const float* __restrict__ b1,
                             const float* __restrict__ W2, const float* __restrict__ b2,
                             const float* __restrict__ gs, const float* __restrict__ bs,
                             float* __restrict__ slots_out, int last) {
    __shared__ float shA[2 * Cn];
    __shared__ float shB[Cn];
    __shared__ float red[16];
    __shared__ float asum_s;
    int r = blockIdx.x, tid = threadIdx.x;

    shB[tid] = g_y[(size_t)r * Cn + tid];
    if (tid == 0) asum_s = g_asum[r] + EPSf;
    __syncthreads();
    // zero accumulators for next iteration (this block owns row r exclusively)
    g_y[(size_t)r * Cn + tid] = 0.f;
    if (tid == 0) g_asum[r] = 0.f;

    float u = gemv_col(Wv, shB, Cn, tid, Cn) / asum_s;

    float s = u, q = u * u;
    blockReduce2(s, q, red);  // internal syncs also fence shB reads
    float mean = s * (1.0f / Cn);
    float rs = rsqrtf(q * (1.0f / Cn) - mean * mean + LNEPS);
    float h = (u - mean) * rs * gu[tid] + bu[tid];
    shB[tid] = h;
    __syncthreads();

    float m0 = gemv_col(W1, shB, Cn, tid, 2 * Cn) + b1[tid];
    float m1 = gemv_col(W1, shB, Cn, tid + Cn, 2 * Cn) + b1[tid + Cn];
    shA[tid] = fmaxf(m0, 0.f);
    shA[tid + Cn] = fmaxf(m1, 0.f);
    __syncthreads();

    float d = gemv_col(W2, shA, 2 * Cn, tid, Cn) + b2[tid];
    float ns = g_slots[(size_t)r * Cn + tid] + d;
    g_slots[(size_t)r * Cn + tid] = ns;
    if (last) {
        slots_out[(size_t)r * Cn + tid] = ns;
        return;
    }
    slots_to_kq(r, ns, gs, bs, shB, red);
}

// ------------------------------------------------------------------
extern "C" void kernel_launch(void* const* d_in, const int* in_sizes, int n_in,
                              void* d_out, int out_size) {
    (void)in_sizes; (void)n_in; (void)out_size;
    const float* feat  = (const float*)d_in[0];
    const float* noise = (const float*)d_in[1];
    const float* Wq    = (const float*)d_in[2];
    const float* Wk    = (const float*)d_in[3];
    const float* Wv    = (const float*)d_in[4];
    const float* scale = (const float*)d_in[5];
    const float* gin   = (const float*)d_in[6];
    const float* bin   = (const float*)d_in[7];
    const float* gs    = (const float*)d_in[8];
    const float* bs    = (const float*)d_in[9];
    const float* gu    = (const float*)d_in[10];
    const float* bu    = (const float*)d_in[11];
    const float* W1    = (const float*)d_in[12];
    const float* b1    = (const float*)d_in[13];
    const float* W2    = (const float*)d_in[14];
    const float* b2    = (const float*)d_in[15];
    const float* nsc   = (const float*)d_in[16];

    float* out = (float*)d_out;
    float* slots_out = out;                   // [B,V,C] first
    float* attn_out = out + Bn * Vn * Cn;     // [B,L,V] second

    zero_buffers<<<160, 256>>>();
    base_reduce<<<dim3(NCHUNK, Bn), 256>>>(feat);
    compute_M<<<Cn, Cn>>>(Wk, Wq, scale);
    init_slots<<<Bn * Vn, Cn>>>(noise, nsc);
    prep_kq<<<Bn * Vn, Cn>>>(gs, bs);
    for (int t = 0; t < Tn; t++) {
        main_pass<<<dim3(Ln / 128, Bn), 256>>>(feat, gin, bin, attn_out, t == Tn - 1);
        chain_kernel<<<Bn * Vn, Cn>>>(Wv, gu, bu, W1, b1, W2, b2, gs, bs,
                                      slots_out, t == Tn - 1);
    }
}

// round 5
// speedup vs baseline: 1.1499x; 1.1469x over previous
#include <cuda_runtime.h>
#include <math.h>

#define Bn 32
#define Ln 4096
#define Cn 256
#define Vn 5
#define Tn 3
#define EPSf 1e-8f
#define LNEPS 1e-5f
#define NCHUNK 16

// ---- scratch (__device__ globals; no allocation allowed) ----
__device__ __align__(16) float  g_basep[NCHUNK][Bn * Cn];
__device__ __align__(16) float2 g_mrs[Bn * Ln];          // per-token (mean, rsigma)
__device__ __align__(16) float  g_slots[Bn * Vn * Cn];
__device__ __align__(16) float  g_kq[Bn * Vn * Cn];      // scale * Wq @ k per slot row
__device__ __align__(16) float  g_M[Cn * Cn];            // M[j][i] = scale * sum_c Wk[j,c]*Wq[i,c]
__device__ __align__(16) float  g_P[Bn * Vn * Cn];       // sum_l (a*rs)*f
__device__ __align__(16) float  g_Q[Bn * Vn];            // sum_l a*rs*mean
__device__ __align__(16) float  g_A[Bn * Vn];            // sum_l a

// ------------------------------------------------------------------
__device__ __forceinline__ void blockReduce2(float& s, float& q, volatile float* red) {
    int lane = threadIdx.x & 31, wid = threadIdx.x >> 5;
#pragma unroll
    for (int o = 16; o; o >>= 1) {
        s += __shfl_xor_sync(0xFFFFFFFFu, s, o);
        q += __shfl_xor_sync(0xFFFFFFFFu, q, o);
    }
    if (lane == 0) { red[wid] = s; red[8 + wid] = q; }
    __syncthreads();
    s = red[0]; q = red[8];
#pragma unroll
    for (int i = 1; i < 8; i++) { s += red[i]; q += red[8 + i]; }
    __syncthreads();
}

__device__ __forceinline__ float gemv_col(const float* __restrict__ W, const float* sh,
                                          int n, int col, int ld) {
    float a0 = 0.f, a1 = 0.f, a2 = 0.f, a3 = 0.f;
#pragma unroll 2
    for (int i = 0; i < n; i += 4) {
        a0 = fmaf(sh[i + 0], W[(size_t)(i + 0) * ld + col], a0);
        a1 = fmaf(sh[i + 1], W[(size_t)(i + 1) * ld + col], a1);
        a2 = fmaf(sh[i + 2], W[(size_t)(i + 2) * ld + col], a2);
        a3 = fmaf(sh[i + 3], W[(size_t)(i + 3) * ld + col], a3);
    }
    return (a0 + a1) + (a2 + a3);
}

// ------------------------------------------------------------------
// base_stats: per-chunk partial feature sums (for slot init) + per-token LN stats
__global__ void __launch_bounds__(256) base_stats(const float* __restrict__ f) {
    __shared__ float bsh[8][Cn];
    int b = blockIdx.y, chunk = blockIdx.x;
    int tid = threadIdx.x, lane = tid & 31, wid = tid >> 5;
    const int RPW = (Ln / NCHUNK) / 8;  // 32 rows per warp
    int l0 = chunk * (Ln / NCHUNK) + wid * RPW;

    float4 a0 = make_float4(0, 0, 0, 0), a1 = make_float4(0, 0, 0, 0);
    for (int i = 0; i < RPW; i++) {
        int l = l0 + i;
        const float4* fr = (const float4*)f + ((size_t)b * Ln + l) * 64;
        float4 f0 = fr[lane], f1 = fr[32 + lane];
        a0.x += f0.x; a0.y += f0.y; a0.z += f0.z; a0.w += f0.w;
        a1.x += f1.x; a1.y += f1.y; a1.z += f1.z; a1.w += f1.w;
        float s = (f0.x + f0.y) + (f0.z + f0.w) + (f1.x + f1.y) + (f1.z + f1.w);
        float q = fmaf(f0.x, f0.x, fmaf(f0.y, f0.y, fmaf(f0.z, f0.z, f0.w * f0.w))) +
                  fmaf(f1.x, f1.x, fmaf(f1.y, f1.y, fmaf(f1.z, f1.z, f1.w * f1.w)));
#pragma unroll
        for (int o = 16; o; o >>= 1) {
            s += __shfl_xor_sync(0xFFFFFFFFu, s, o);
            q += __shfl_xor_sync(0xFFFFFFFFu, q, o);
        }
        float mean = s * (1.0f / Cn);
        float rs = rsqrtf(q * (1.0f / Cn) - mean * mean + LNEPS);
        if (lane == 0) g_mrs[(size_t)b * Ln + l] = make_float2(mean, rs);
    }
    ((float4*)&bsh[wid][0])[lane] = a0;
    ((float4*)&bsh[wid][0])[32 + lane] = a1;
    __syncthreads();
    float s = 0.f;
#pragma unroll
    for (int w = 0; w < 8; w++) s += bsh[w][tid];
    g_basep[chunk][b * Cn + tid] = s;
}

// compute M + zero accumulators
__global__ void computeM_zero(const float* __restrict__ Wk, const float* __restrict__ Wq,
                              const float* __restrict__ scale_p) {
    int idx = blockIdx.x * 256 + threadIdx.x;
    if (idx < Bn * Vn * Cn) g_P[idx] = 0.f;
    if (idx < Bn * Vn) { g_Q[idx] = 0.f; g_A[idx] = 0.f; }

    __shared__ float4 wk4[Cn / 4];
    int cj = blockIdx.x, ci = threadIdx.x;
    if (threadIdx.x < 64) wk4[threadIdx.x] = ((const float4*)Wk)[(size_t)cj * 64 + threadIdx.x];
    __syncthreads();
    const float4* wq4 = (const float4*)Wq + (size_t)ci * 64;
    float a0 = 0, a1 = 0, a2 = 0, a3 = 0;
#pragma unroll 8
    for (int qx = 0; qx < 64; qx++) {
        float4 wv = wq4[qx]; float4 kv = wk4[qx];
        a0 = fmaf(kv.x, wv.x, a0); a1 = fmaf(kv.y, wv.y, a1);
        a2 = fmaf(kv.z, wv.z, a2); a3 = fmaf(kv.w, wv.w, a3);
    }
    g_M[(size_t)cj * Cn + ci] = scale_p[0] * ((a0 + a1) + (a2 + a3));
}

// init slots (base mean + noise) then kq = LN(slots) @ M
__global__ void init_prep(const float* __restrict__ noise, const float* __restrict__ ns_p,
                          const float* __restrict__ gs, const float* __restrict__ bs) {
    __shared__ float sh[Cn];
    __shared__ float red[16];
    int r = blockIdx.x, tid = threadIdx.x, b = r / Vn;
    float s = 0.f;
#pragma unroll
    for (int k = 0; k < NCHUNK; k++) s += g_basep[k][b * Cn + tid];
    float slotv = s * (1.0f / Ln) + noise[(size_t)r * Cn + tid] * fabsf(ns_p[0]);
    g_slots[(size_t)r * Cn + tid] = slotv;

    float ss = slotv, qq = slotv * slotv;
    blockReduce2(ss, qq, red);
    float mean = ss * (1.0f / Cn);
    float rs = rsqrtf(qq * (1.0f / Cn) - mean * mean + LNEPS);
    sh[tid] = (slotv - mean) * rs * gs[tid] + bs[tid];
    __syncthreads();
    g_kq[(size_t)r * Cn + tid] = gemv_col(g_M, sh, Cn, tid, Cn);
}

// ------------------------------------------------------------------
// main streaming pass
__global__ void __launch_bounds__(256)
main_pass(const float* __restrict__ feat, const float* __restrict__ gin,
          const float* __restrict__ bin, float* __restrict__ attn_out, int write_attn) {
    __shared__ float Pw[8][Vn * Cn];      // per-warp P partials
    __shared__ float GBs[Vn][2];          // G_v, B_v
    __shared__ float Aw[8][Vn], Qw[8][Vn];

    int b = blockIdx.y;
    int tid = threadIdx.x, lane = tid & 31, wid = tid >> 5;

    // per-slot scalars G_v = g·kq_v, B_v = b·kq_v (warps 0..4)
    if (wid < Vn) {
        int v = wid;
        float gp = 0.f, bp = 0.f;
#pragma unroll
        for (int j = 0; j < 8; j++) {
            int c = lane + 32 * j;
            float kq = g_kq[((size_t)b * Vn + v) * Cn + c];
            gp = fmaf(gin[c], kq, gp);
            bp = fmaf(bin[c], kq, bp);
        }
#pragma unroll
        for (int o = 16; o; o >>= 1) {
            gp += __shfl_xor_sync(0xFFFFFFFFu, gp, o);
            bp += __shfl_xor_sync(0xFFFFFFFFu, bp, o);
        }
        if (lane == 0) { GBs[v][0] = gp; GBs[v][1] = bp; }
    }

    // g∘kq in registers
    float4 gin0 = ((const float4*)gin)[lane], gin1 = ((const float4*)gin)[32 + lane];
    float4 gk0[Vn], gk1[Vn];
#pragma unroll
    for (int v = 0; v < Vn; v++) {
        float4 k0 = ((const float4*)g_kq)[((size_t)b * Vn + v) * 64 + lane];
        float4 k1 = ((const float4*)g_kq)[((size_t)b * Vn + v) * 64 + 32 + lane];
        gk0[v] = make_float4(gin0.x * k0.x, gin0.y * k0.y, gin0.z * k0.z, gin0.w * k0.w);
        gk1[v] = make_float4(gin1.x * k1.x, gin1.y * k1.y, gin1.z * k1.z, gin1.w * k1.w);
    }
    __syncthreads();

    float4 p0[Vn], p1[Vn];
    float Aacc[Vn], Qacc[Vn];
#pragma unroll
    for (int v = 0; v < Vn; v++) {
        p0[v] = make_float4(0, 0, 0, 0); p1[v] = make_float4(0, 0, 0, 0);
        Aacc[v] = 0.f; Qacc[v] = 0.f;
    }

    int l0 = blockIdx.x * 128 + wid * 16;
    for (int i = 0; i < 16; i++) {
        int l = l0 + i;
        const float4* fr = (const float4*)feat + ((size_t)b * Ln + l) * 64;
        float4 f0 = fr[lane], f1 = fr[32 + lane];
        float2 mr = g_mrs[(size_t)b * Ln + l];

        float dv[Vn];
#pragma unroll
        for (int v = 0; v < Vn; v++) {
            float t = f0.x * gk0[v].x;
            t = fmaf(f0.y, gk0[v].y, t); t = fmaf(f0.z, gk0[v].z, t); t = fmaf(f0.w, gk0[v].w, t);
            t = fmaf(f1.x, gk1[v].x, t); t = fmaf(f1.y, gk1[v].y, t);
            t = fmaf(f1.z, gk1[v].z, t); t = fmaf(f1.w, gk1[v].w, t);
            dv[v] = t;
        }
#pragma unroll
        for (int o = 16; o; o >>= 1) {
#pragma unroll
            for (int v = 0; v < Vn; v++)
                dv[v] += __shfl_xor_sync(0xFFFFFFFFu, dv[v], o);
        }
        float rm = mr.y * mr.x;  // rs*mean
        float lg[Vn];
#pragma unroll
        for (int v = 0; v < Vn; v++)
            lg[v] = fmaf(mr.y, dv[v], fmaf(-rm, GBs[v][0], GBs[v][1]));
        float mx = lg[0];
#pragma unroll
        for (int v = 1; v < Vn; v++) mx = fmaxf(mx, lg[v]);
        float e[Vn], se = 0.f;
#pragma unroll
        for (int v = 0; v < Vn; v++) { e[v] = __expf(lg[v] - mx); se += e[v]; }
        float inv = 1.0f / se;
#pragma unroll
        for (int v = 0; v < Vn; v++) {
            float a = e[v] * inv;
            float w = a * mr.y;
            e[v] = a;
            Aacc[v] += a;
            Qacc[v] = fmaf(w, mr.x, Qacc[v]);
            p0[v].x = fmaf(w, f0.x, p0[v].x); p0[v].y = fmaf(w, f0.y, p0[v].y);
            p0[v].z = fmaf(w, f0.z, p0[v].z); p0[v].w = fmaf(w, f0.w, p0[v].w);
            p1[v].x = fmaf(w, f1.x, p1[v].x); p1[v].y = fmaf(w, f1.y, p1[v].y);
            p1[v].z = fmaf(w, f1.z, p1[v].z); p1[v].w = fmaf(w, f1.w, p1[v].w);
        }
        if (write_attn && lane < Vn) {
            float av = e[0];
            if (lane == 1) av = e[1];
            else if (lane == 2) av = e[2];
            else if (lane == 3) av = e[3];
            else if (lane == 4) av = e[4];
            attn_out[((size_t)b * Ln + l) * Vn + lane] = av;
        }
    }

    // epilogue: per-warp partials -> smem -> global atomics (once per block)
#pragma unroll
    for (int v = 0; v < Vn; v++) {
        ((float4*)&Pw[wid][v * Cn])[lane] = p0[v];
        ((float4*)&Pw[wid][v * Cn])[32 + lane] = p1[v];
    }
    if (lane == 0) {
#pragma unroll
        for (int v = 0; v < Vn; v++) { Aw[wid][v] = Aacc[v]; Qw[wid][v] = Qacc[v]; }
    }
    __syncthreads();
    for (int idx = tid; idx < Vn * Cn; idx += 256) {
        float s = 0.f;
#pragma unroll
        for (int w = 0; w < 8; w++) s += Pw[w][idx];
        atomicAdd(&g_P[(size_t)b * Vn * Cn + idx], s);
    }
    if (tid < Vn) {
        float sa = 0.f, sq = 0.f;
#pragma unroll
        for (int w = 0; w < 8; w++) { sa += Aw[w][tid]; sq += Qw[w][tid]; }
        atomicAdd(&g_A[b * Vn + tid], sa);
        atomicAdd(&g_Q[b * Vn + tid], sq);
    }
}

// ------------------------------------------------------------------
// chain: one block per batch; rank-5 GEMMs with float4 loads.
// thread layout per GEMM: ks = tid&7 (k-slice), cg = tid>>3 (0..63, 4 cols each)
#define GEMM5(Wptr, KDIM, IN, INLD, COLOFF, WLD)                                 \
    {                                                                            \
        _Pragma("unroll")                                                        \
        for (int v = 0; v < Vn; v++) acc[v] = make_float4(0, 0, 0, 0);           \
        _Pragma("unroll 4")                                                      \
        for (int j = 0; j < (KDIM) / 8; j++) {                                   \
            int k = ks + 8 * j;                                                  \
            float4 w4 = ((const float4*)(Wptr))[(size_t)k * ((WLD) / 4) + (COLOFF) / 4 + cg]; \
            _Pragma("unroll")                                                    \
            for (int v = 0; v < Vn; v++) {                                       \
                float sv = IN[v * (INLD) + k];                                   \
                acc[v].x = fmaf(sv, w4.x, acc[v].x);                             \
                acc[v].y = fmaf(sv, w4.y, acc[v].y);                             \
                acc[v].z = fmaf(sv, w4.z, acc[v].z);                             \
                acc[v].w = fmaf(sv, w4.w, acc[v].w);                             \
            }                                                                    \
        }                                                                        \
        _Pragma("unroll")                                                        \
        for (int o = 1; o < 8; o <<= 1) {                                        \
            _Pragma("unroll")                                                    \
            for (int v = 0; v < Vn; v++) {                                       \
                acc[v].x += __shfl_xor_sync(0xFFFFFFFFu, acc[v].x, o);           \
                acc[v].y += __shfl_xor_sync(0xFFFFFFFFu, acc[v].y, o);           \
                acc[v].z += __shfl_xor_sync(0xFFFFFFFFu, acc[v].z, o);           \
                acc[v].w += __shfl_xor_sync(0xFFFFFFFFu, acc[v].w, o);           \
            }                                                                    \
        }                                                                        \
    }

__global__ void __launch_bounds__(512)
chain2(const float* __restrict__ Wv,
       const float* __restrict__ gu, const float* __restrict__ bu,
       const float* __restrict__ W1, const float* __restrict__ b1,
       const float* __restrict__ W2, const float* __restrict__ b2,
       const float* __restrict__ gs, const float* __restrict__ bs,
       const float* __restrict__ gin, const float* __restrict__ bin,
       float* __restrict__ slots_out, int last) {
    __shared__ float bufA[Vn * 2 * Cn];
    __shared__ float bufB[Vn * 2 * Cn];
    __shared__ float mrsh[Vn][2];
    __shared__ float asum_s[Vn];

    int b = blockIdx.x, tid = threadIdx.x;
    int lane = tid & 31, wid = tid >> 5;
    int ks = tid & 7, cg = tid >> 3;
    float4 acc[Vn];

    // y_vc = g_c*(P - Q) + b_c*A  -> bufA (256-wide rows)
    if (tid < Vn) asum_s[tid] = g_A[b * Vn + tid] + EPSf;
    for (int idx = tid; idx < Vn * Cn; idx += 512) {
        int v = idx >> 8, c = idx & 255;
        float A = g_A[b * Vn + v], Q = g_Q[b * Vn + v];
        float Pv = g_P[(size_t)b * Vn * Cn + idx];
        bufA[idx] = fmaf(gin[c], Pv - Q, bin[c] * A);
        g_P[(size_t)b * Vn * Cn + idx] = 0.f;
    }
    __syncthreads();
    if (tid < Vn) { g_A[b * Vn + tid] = 0.f; g_Q[b * Vn + tid] = 0.f; }

    // u = y @ Wv / asum -> bufB
    GEMM5(Wv, Cn, bufA, Cn, 0, Cn);
    if (ks == 0) {
#pragma unroll
        for (int v = 0; v < Vn; v++) {
            float ia = 1.0f / asum_s[v];
            ((float4*)&bufB[v * Cn])[cg] =
                make_float4(acc[v].x * ia, acc[v].y * ia, acc[v].z * ia, acc[v].w * ia);
        }
    }
    __syncthreads();

    // LN(u) with gu,bu -> bufA
    if (wid < Vn) {
        int v = wid;
        float s = 0.f, q = 0.f;
#pragma unroll
        for (int j = 0; j < 8; j++) {
            float x = bufB[v * Cn + lane + 32 * j];
            s += x; q = fmaf(x, x, q);
        }
#pragma unroll
        for (int o = 16; o; o >>= 1) {
            s += __shfl_xor_sync(0xFFFFFFFFu, s, o);
            q += __shfl_xor_sync(0xFFFFFFFFu, q, o);
        }
        float mean = s * (1.0f / Cn);
        float rs = rsqrtf(q * (1.0f / Cn) - mean * mean + LNEPS);
        if (lane == 0) { mrsh[v][0] = mean; mrsh[v][1] = rs; }
    }
    __syncthreads();
    for (int idx = tid; idx < Vn * Cn; idx += 512) {
        int v = idx >> 8, c = idx & 255;
        bufA[idx] = fmaf((bufB[idx] - mrsh[v][0]) * mrsh[v][1], gu[c], bu[c]);
    }
    __syncthreads();

    // hh = relu(h @ W1 + b1) -> bufB (512-wide rows), two column halves
#pragma unroll
    for (int h = 0; h < 2; h++) {
        GEMM5(W1, Cn, bufA, Cn, h * Cn, 2 * Cn);
        if (ks == 0) {
            float4 bb = ((const float4*)b1)[h * 64 + cg];
#pragma unroll
            for (int v = 0; v < Vn; v++) {
                ((float4*)&bufB[v * 2 * Cn + h * Cn])[cg] =
                    make_float4(fmaxf(acc[v].x + bb.x, 0.f), fmaxf(acc[v].y + bb.y, 0.f),
                                fmaxf(acc[v].z + bb.z, 0.f), fmaxf(acc[v].w + bb.w, 0.f));
            }
        }
    }
    __syncthreads();

    // d = hh @ W2 + b2; slots += d -> global, bufA
    GEMM5(W2, 2 * Cn, bufB, 2 * Cn, 0, Cn);
    if (ks == 0) {
        float4 bb = ((const float4*)b2)[cg];
#pragma unroll
        for (int v = 0; v < Vn; v++) {
            float4 sl = ((const float4*)g_slots)[((size_t)b * Vn + v) * 64 + cg];
            float4 ns = make_float4(sl.x + acc[v].x + bb.x, sl.y + acc[v].y + bb.y,
                                    sl.z + acc[v].z + bb.z, sl.w + acc[v].w + bb.w);
            ((float4*)g_slots)[((size_t)b * Vn + v) * 64 + cg] = ns;
            if (last) ((float4*)slots_out)[((size_t)b * Vn + v) * 64 + cg] = ns;
            ((float4*)&bufA[v * Cn])[cg] = ns;
        }
    }
    if (last) return;
    __syncthreads();

    // LN(slots) with gs,bs -> bufB; kq = · @ M -> g_kq
    if (wid < Vn) {
        int v = wid;
        float s = 0.f, q = 0.f;
#pragma unroll
        for (int j = 0; j < 8; j++) {
            float x = bufA[v * Cn + lane + 32 * j];
            s += x; q = fmaf(x, x, q);
        }
#pragma unroll
        for (int o = 16; o; o >>= 1) {
            s += __shfl_xor_sync(0xFFFFFFFFu, s, o);
            q += __shfl_xor_sync(0xFFFFFFFFu, q, o);
        }
        float mean = s * (1.0f / Cn);
        float rs = rsqrtf(q * (1.0f / Cn) - mean * mean + LNEPS);
        if (lane == 0) { mrsh[v][0] = mean; mrsh[v][1] = rs; }
    }
    __syncthreads();
    for (int idx = tid; idx < Vn * Cn; idx += 512) {
        int v = idx >> 8, c = idx & 255;
        bufB[idx] = fmaf((bufA[idx] - mrsh[v][0]) * mrsh[v][1], gs[c], bs[c]);
    }
    __syncthreads();
    GEMM5(g_M, Cn, bufB, Cn, 0, Cn);
    if (ks == 0) {
#pragma unroll
        for (int v = 0; v < Vn; v++)
            ((float4*)g_kq)[((size_t)b * Vn + v) * 64 + cg] = acc[v];
    }
}

// ------------------------------------------------------------------
extern "C" void kernel_launch(void* const* d_in, const int* in_sizes, int n_in,
                              void* d_out, int out_size) {
    (void)in_sizes; (void)n_in; (void)out_size;
    const float* feat  = (const float*)d_in[0];
    const float* noise = (const float*)d_in[1];
    const float* Wq    = (const float*)d_in[2];
    const float* Wk    = (const float*)d_in[3];
    const float* Wv    = (const float*)d_in[4];
    const float* scale = (const float*)d_in[5];
    const float* gin   = (const float*)d_in[6];
    const float* bin   = (const float*)d_in[7];
    const float* gs    = (const float*)d_in[8];
    const float* bs    = (const float*)d_in[9];
    const float* gu    = (const float*)d_in[10];
    const float* bu    = (const float*)d_in[11];
    const float* W1    = (const float*)d_in[12];
    const float* b1    = (const float*)d_in[13];
    const float* W2    = (const float*)d_in[14];
    const float* b2    = (const float*)d_in[15];
    const float* nsc   = (const float*)d_in[16];

    float* out = (float*)d_out;
    float* slots_out = out;                   // [B,V,C]
    float* attn_out = out + Bn * Vn * Cn;     // [B,L,V]

    base_stats<<<dim3(NCHUNK, Bn), 256>>>(feat);
    computeM_zero<<<Cn, Cn>>>(Wk, Wq, scale);
    init_prep<<<Bn * Vn, Cn>>>(noise, nsc, gs, bs);
    for (int t = 0; t < Tn; t++) {
        main_pass<<<dim3(Ln / 128, Bn), 256>>>(feat, gin, bin, attn_out, t == Tn - 1);
        chain2<<<Bn, 512>>>(Wv, gu, bu, W1, b1, W2, b2, gs, bs, gin, bin,
                            slots_out, t == Tn - 1);
    }
}

// round 6
// speedup vs baseline: 1.3884x; 1.2075x over previous
#include <cuda_runtime.h>
#include <math.h>

#define Bn 32
#define Ln 4096
#define Cn 256
#define Vn 5
#define Tn 3
#define EPSf 1e-8f
#define LNEPS 1e-5f
#define NCHUNK 64

// ---- scratch (__device__ globals; no allocation allowed) ----
__device__ __align__(16) float  g_basep[NCHUNK][Bn * Cn];
__device__ __align__(16) float2 g_mrs[Bn * Ln];          // per-token (mean, rsigma)
__device__ __align__(16) float  g_slots[Bn * Vn * Cn];
__device__ __align__(16) float  g_kq[Bn * Vn * Cn];      // scale * Wq @ k per slot row
__device__ __align__(16) float  g_M[Cn * Cn];            // M[j][i] = scale * sum_c Wk[j,c]*Wq[i,c]
__device__ __align__(16) float  g_P[Bn * Vn * Cn];       // sum_l (a*rs)*f
__device__ __align__(16) float  g_Q[Bn * Vn];            // sum_l a*rs*mean
__device__ __align__(16) float  g_A[Bn * Vn];            // sum_l a

// ------------------------------------------------------------------
__device__ __forceinline__ void blockReduce2(float& s, float& q, volatile float* red) {
    int lane = threadIdx.x & 31, wid = threadIdx.x >> 5;
#pragma unroll
    for (int o = 16; o; o >>= 1) {
        s += __shfl_xor_sync(0xFFFFFFFFu, s, o);
        q += __shfl_xor_sync(0xFFFFFFFFu, q, o);
    }
    if (lane == 0) { red[wid] = s; red[8 + wid] = q; }
    __syncthreads();
    s = red[0]; q = red[8];
#pragma unroll
    for (int i = 1; i < 8; i++) { s += red[i]; q += red[8 + i]; }
    __syncthreads();
}

__device__ __forceinline__ float gemv_col(const float* __restrict__ W, const float* sh,
                                          int n, int col, int ld) {
    float a0 = 0.f, a1 = 0.f, a2 = 0.f, a3 = 0.f;
#pragma unroll 2
    for (int i = 0; i < n; i += 4) {
        a0 = fmaf(sh[i + 0], W[(size_t)(i + 0) * ld + col], a0);
        a1 = fmaf(sh[i + 1], W[(size_t)(i + 1) * ld + col], a1);
        a2 = fmaf(sh[i + 2], W[(size_t)(i + 2) * ld + col], a2);
        a3 = fmaf(sh[i + 3], W[(size_t)(i + 3) * ld + col], a3);
    }
    return (a0 + a1) + (a2 + a3);
}

// ------------------------------------------------------------------
// base_stats: per-chunk partial feature sums + per-token LN stats.
// 2 rows per iteration -> 4 independent butterfly chains for latency hiding.
__global__ void __launch_bounds__(256) base_stats(const float* __restrict__ f) {
    __shared__ float bsh[8][Cn];
    int b = blockIdx.y, chunk = blockIdx.x;
    int tid = threadIdx.x, lane = tid & 31, wid = tid >> 5;
    const int RPW = (Ln / NCHUNK) / 8;  // 8 rows per warp
    int l0 = chunk * (Ln / NCHUNK) + wid * RPW;

    float4 a0 = make_float4(0, 0, 0, 0), a1 = make_float4(0, 0, 0, 0);
#pragma unroll
    for (int i = 0; i < RPW; i += 2) {
        int l = l0 + i;
        const float4* frA = (const float4*)f + ((size_t)b * Ln + l) * 64;
        const float4* frB = (const float4*)f + ((size_t)b * Ln + l + 1) * 64;
        float4 fa0 = frA[lane], fa1 = frA[32 + lane];
        float4 fb0 = frB[lane], fb1 = frB[32 + lane];

        a0.x += fa0.x + fb0.x; a0.y += fa0.y + fb0.y;
        a0.z += fa0.z + fb0.z; a0.w += fa0.w + fb0.w;
        a1.x += fa1.x + fb1.x; a1.y += fa1.y + fb1.y;
        a1.z += fa1.z + fb1.z; a1.w += fa1.w + fb1.w;

        float sA = (fa0.x + fa0.y) + (fa0.z + fa0.w) + (fa1.x + fa1.y) + (fa1.z + fa1.w);
        float qA = fmaf(fa0.x, fa0.x, fmaf(fa0.y, fa0.y, fmaf(fa0.z, fa0.z, fa0.w * fa0.w))) +
                   fmaf(fa1.x, fa1.x, fmaf(fa1.y, fa1.y, fmaf(fa1.z, fa1.z, fa1.w * fa1.w)));
        float sB = (fb0.x + fb0.y) + (fb0.z + fb0.w) + (fb1.x + fb1.y) + (fb1.z + fb1.w);
        float qB = fmaf(fb0.x, fb0.x, fmaf(fb0.y, fb0.y, fmaf(fb0.z, fb0.z, fb0.w * fb0.w))) +
                   fmaf(fb1.x, fb1.x, fmaf(fb1.y, fb1.y, fmaf(fb1.z, fb1.z, fb1.w * fb1.w)));
#pragma unroll
        for (int o = 16; o; o >>= 1) {
            sA += __shfl_xor_sync(0xFFFFFFFFu, sA, o);
            qA += __shfl_xor_sync(0xFFFFFFFFu, qA, o);
            sB += __shfl_xor_sync(0xFFFFFFFFu, sB, o);
            qB += __shfl_xor_sync(0xFFFFFFFFu, qB, o);
        }
        if (lane == 0) {
            float mA = sA * (1.0f / Cn);
            float mB = sB * (1.0f / Cn);
            g_mrs[(size_t)b * Ln + l] =
                make_float2(mA, rsqrtf(qA * (1.0f / Cn) - mA * mA + LNEPS));
            g_mrs[(size_t)b * Ln + l + 1] =
                make_float2(mB, rsqrtf(qB * (1.0f / Cn) - mB * mB + LNEPS));
        }
    }
    ((float4*)&bsh[wid][0])[lane] = a0;
    ((float4*)&bsh[wid][0])[32 + lane] = a1;
    __syncthreads();
    float s = 0.f;
#pragma unroll
    for (int w = 0; w < 8; w++) s += bsh[w][tid];
    g_basep[chunk][b * Cn + tid] = s;
}

// compute M + zero accumulators
__global__ void computeM_zero(const float* __restrict__ Wk, const float* __restrict__ Wq,
                              const float* __restrict__ scale_p) {
    int idx = blockIdx.x * 256 + threadIdx.x;
    if (idx < Bn * Vn * Cn) g_P[idx] = 0.f;
    if (idx < Bn * Vn) { g_Q[idx] = 0.f; g_A[idx] = 0.f; }

    __shared__ float4 wk4[Cn / 4];
    int cj = blockIdx.x, ci = threadIdx.x;
    if (threadIdx.x < 64) wk4[threadIdx.x] = ((const float4*)Wk)[(size_t)cj * 64 + threadIdx.x];
    __syncthreads();
    const float4* wq4 = (const float4*)Wq + (size_t)ci * 64;
    float a0 = 0, a1 = 0, a2 = 0, a3 = 0;
#pragma unroll 8
    for (int qx = 0; qx < 64; qx++) {
        float4 wv = wq4[qx]; float4 kv = wk4[qx];
        a0 = fmaf(kv.x, wv.x, a0); a1 = fmaf(kv.y, wv.y, a1);
        a2 = fmaf(kv.z, wv.z, a2); a3 = fmaf(kv.w, wv.w, a3);
    }
    g_M[(size_t)cj * Cn + ci] = scale_p[0] * ((a0 + a1) + (a2 + a3));
}

// init slots (base mean + noise) then kq = LN(slots) @ M
__global__ void init_prep(const float* __restrict__ noise, const float* __restrict__ ns_p,
                          const float* __restrict__ gs, const float* __restrict__ bs) {
    __shared__ float sh[Cn];
    __shared__ float red[16];
    int r = blockIdx.x, tid = threadIdx.x, b = r / Vn;
    float s = 0.f;
#pragma unroll
    for (int k = 0; k < NCHUNK; k++) s += g_basep[k][b * Cn + tid];
    float slotv = s * (1.0f / Ln) + noise[(size_t)r * Cn + tid] * fabsf(ns_p[0]);
    g_slots[(size_t)r * Cn + tid] = slotv;

    float ss = slotv, qq = slotv * slotv;
    blockReduce2(ss, qq, red);
    float mean = ss * (1.0f / Cn);
    float rs = rsqrtf(qq * (1.0f / Cn) - mean * mean + LNEPS);
    sh[tid] = (slotv - mean) * rs * gs[tid] + bs[tid];
    __syncthreads();
    g_kq[(size_t)r * Cn + tid] = gemv_col(g_M, sh, Cn, tid, Cn);
}

// ------------------------------------------------------------------
// main streaming pass  (force 2 CTAs/SM: regs capped at 128)
__global__ void __launch_bounds__(256, 2)
main_pass(const float* __restrict__ feat, const float* __restrict__ gin,
          const float* __restrict__ bin, float* __restrict__ attn_out, int write_attn) {
    __shared__ float Pw[8][Vn * Cn];      // per-warp P partials
    __shared__ float GBs[Vn][2];          // G_v, B_v
    __shared__ float Aw[8][Vn], Qw[8][Vn];

    int b = blockIdx.y;
    int tid = threadIdx.x, lane = tid & 31, wid = tid >> 5;

    // per-slot scalars G_v = g·kq_v, B_v = b·kq_v (warps 0..4)
    if (wid < Vn) {
        int v = wid;
        float gp = 0.f, bp = 0.f;
#pragma unroll
        for (int j = 0; j < 8; j++) {
            int c = lane + 32 * j;
            float kq = g_kq[((size_t)b * Vn + v) * Cn + c];
            gp = fmaf(gin[c], kq, gp);
            bp = fmaf(bin[c], kq, bp);
        }
#pragma unroll
        for (int o = 16; o; o >>= 1) {
            gp += __shfl_xor_sync(0xFFFFFFFFu, gp, o);
            bp += __shfl_xor_sync(0xFFFFFFFFu, bp, o);
        }
        if (lane == 0) { GBs[v][0] = gp; GBs[v][1] = bp; }
    }

    // g∘kq in registers
    float4 gin0 = ((const float4*)gin)[lane], gin1 = ((const float4*)gin)[32 + lane];
    float4 gk0[Vn], gk1[Vn];
#pragma unroll
    for (int v = 0; v < Vn; v++) {
        float4 k0 = ((const float4*)g_kq)[((size_t)b * Vn + v) * 64 + lane];
        float4 k1 = ((const float4*)g_kq)[((size_t)b * Vn + v) * 64 + 32 + lane];
        gk0[v] = make_float4(gin0.x * k0.x, gin0.y * k0.y, gin0.z * k0.z, gin0.w * k0.w);
        gk1[v] = make_float4(gin1.x * k1.x, gin1.y * k1.y, gin1.z * k1.z, gin1.w * k1.w);
    }
    __syncthreads();

    float4 p0[Vn], p1[Vn];
    float Aacc[Vn], Qacc[Vn];
#pragma unroll
    for (int v = 0; v < Vn; v++) {
        p0[v] = make_float4(0, 0, 0, 0); p1[v] = make_float4(0, 0, 0, 0);
        Aacc[v] = 0.f; Qacc[v] = 0.f;
    }

    int l0 = blockIdx.x * 128 + wid * 16;
    for (int i = 0; i < 16; i++) {
        int l = l0 + i;
        const float4* fr = (const float4*)feat + ((size_t)b * Ln + l) * 64;
        float4 f0 = fr[lane], f1 = fr[32 + lane];
        float2 mr = g_mrs[(size_t)b * Ln + l];

        float dv[Vn];
#pragma unroll
        for (int v = 0; v < Vn; v++) {
            float t = f0.x * gk0[v].x;
            t = fmaf(f0.y, gk0[v].y, t); t = fmaf(f0.z, gk0[v].z, t); t = fmaf(f0.w, gk0[v].w, t);
            t = fmaf(f1.x, gk1[v].x, t); t = fmaf(f1.y, gk1[v].y, t);
            t = fmaf(f1.z, gk1[v].z, t); t = fmaf(f1.w, gk1[v].w, t);
            dv[v] = t;
        }
#pragma unroll
        for (int o = 16; o; o >>= 1) {
#pragma unroll
            for (int v = 0; v < Vn; v++)
                dv[v] += __shfl_xor_sync(0xFFFFFFFFu, dv[v], o);
        }
        float rm = mr.y * mr.x;  // rs*mean
        float lg[Vn];
#pragma unroll
        for (int v = 0; v < Vn; v++)
            lg[v] = fmaf(mr.y, dv[v], fmaf(-rm, GBs[v][0], GBs[v][1]));
        float mx = lg[0];
#pragma unroll
        for (int v = 1; v < Vn; v++) mx = fmaxf(mx, lg[v]);
        float e[Vn], se = 0.f;
#pragma unroll
        for (int v = 0; v < Vn; v++) { e[v] = __expf(lg[v] - mx); se += e[v]; }
        float inv = 1.0f / se;
#pragma unroll
        for (int v = 0; v < Vn; v++) {
            float a = e[v] * inv;
            float w = a * mr.y;
            e[v] = a;
            Aacc[v] += a;
            Qacc[v] = fmaf(w, mr.x, Qacc[v]);
            p0[v].x = fmaf(w, f0.x, p0[v].x); p0[v].y = fmaf(w, f0.y, p0[v].y);
            p0[v].z = fmaf(w, f0.z, p0[v].z); p0[v].w = fmaf(w, f0.w, p0[v].w);
            p1[v].x = fmaf(w, f1.x, p1[v].x); p1[v].y = fmaf(w, f1.y, p1[v].y);
            p1[v].z = fmaf(w, f1.z, p1[v].z); p1[v].w = fmaf(w, f1.w, p1[v].w);
        }
        if (write_attn && lane < Vn) {
            float av = e[0];
            if (lane == 1) av = e[1];
            else if (lane == 2) av = e[2];
            else if (lane == 3) av = e[3];
            else if (lane == 4) av = e[4];
            attn_out[((size_t)b * Ln + l) * Vn + lane] = av;
        }
    }

    // epilogue: per-warp partials -> smem -> global atomics (once per block)
#pragma unroll
    for (int v = 0; v < Vn; v++) {
        ((float4*)&Pw[wid][v * Cn])[lane] = p0[v];
        ((float4*)&Pw[wid][v * Cn])[32 + lane] = p1[v];
    }
    if (lane == 0) {
#pragma unroll
        for (int v = 0; v < Vn; v++) { Aw[wid][v] = Aacc[v]; Qw[wid][v] = Qacc[v]; }
    }
    __syncthreads();
    for (int idx = tid; idx < Vn * Cn; idx += 256) {
        float s = 0.f;
#pragma unroll
        for (int w = 0; w < 8; w++) s += Pw[w][idx];
        atomicAdd(&g_P[(size_t)b * Vn * Cn + idx], s);
    }
    if (tid < Vn) {
        float sa = 0.f, sq = 0.f;
#pragma unroll
        for (int w = 0; w < 8; w++) { sa += Aw[w][tid]; sq += Qw[w][tid]; }
        atomicAdd(&g_A[b * Vn + tid], sa);
        atomicAdd(&g_Q[b * Vn + tid], sq);
    }
}

// ------------------------------------------------------------------
// chain: one block per batch; rank-5 GEMMs with float4 loads.
#define GEMM5(Wptr, KDIM, IN, INLD, COLOFF, WLD)                                 \
    {                                                                            \
        _Pragma("unroll")                                                        \
        for (int v = 0; v < Vn; v++) acc[v] = make_float4(0, 0, 0, 0);           \
        _Pragma("unroll 4")                                                      \
        for (int j = 0; j < (KDIM) / 8; j++) {                                   \
            int k = ks + 8 * j;                                                  \
            float4 w4 = ((const float4*)(Wptr))[(size_t)k * ((WLD) / 4) + (COLOFF) / 4 + cg]; \
            _Pragma("unroll")                                                    \
            for (int v = 0; v < Vn; v++) {                                       \
                float sv = IN[v * (INLD) + k];                                   \
                acc[v].x = fmaf(sv, w4.x, acc[v].x);                             \
                acc[v].y = fmaf(sv, w4.y, acc[v].y);                             \
                acc[v].z = fmaf(sv, w4.z, acc[v].z);                             \
                acc[v].w = fmaf(sv, w4.w, acc[v].w);                             \
            }                                                                    \
        }                                                                        \
        _Pragma("unroll")                                                        \
        for (int o = 1; o < 8; o <<= 1) {                                        \
            _Pragma("unroll")                                                    \
            for (int v = 0; v < Vn; v++) {                                       \
                acc[v].x += __shfl_xor_sync(0xFFFFFFFFu, acc[v].x, o);           \
                acc[v].y += __shfl_xor_sync(0xFFFFFFFFu, acc[v].y, o);           \
                acc[v].z += __shfl_xor_sync(0xFFFFFFFFu, acc[v].z, o);           \
                acc[v].w += __shfl_xor_sync(0xFFFFFFFFu, acc[v].w, o);           \
            }                                                                    \
        }                                                                        \
    }

__global__ void __launch_bounds__(512)
chain2(const float* __restrict__ Wv,
       const float* __restrict__ gu, const float* __restrict__ bu,
       const float* __restrict__ W1, const float* __restrict__ b1,
       const float* __restrict__ W2, const float* __restrict__ b2,
       const float* __restrict__ gs, const float* __restrict__ bs,
       const float* __restrict__ gin, const float* __restrict__ bin,
       float* __restrict__ slots_out, int last) {
    __shared__ float bufA[Vn * 2 * Cn];
    __shared__ float bufB[Vn * 2 * Cn];
    __shared__ float mrsh[Vn][2];
    __shared__ float asum_s[Vn];

    int b = blockIdx.x, tid = threadIdx.x;
    int lane = tid & 31, wid = tid >> 5;
    int ks = tid & 7, cg = tid >> 3;
    float4 acc[Vn];

    // y_vc = g_c*(P - Q) + b_c*A  -> bufA
    if (tid < Vn) asum_s[tid] = g_A[b * Vn + tid] + EPSf;
    for (int idx = tid; idx < Vn * Cn; idx += 512) {
        int v = idx >> 8, c = idx & 255;
        float A = g_A[b * Vn + v], Q = g_Q[b * Vn + v];
        float Pv = g_P[(size_t)b * Vn * Cn + idx];
        bufA[idx] = fmaf(gin[c], Pv - Q, bin[c] * A);
        g_P[(size_t)b * Vn * Cn + idx] = 0.f;
    }
    __syncthreads();
    if (tid < Vn) { g_A[b * Vn + tid] = 0.f; g_Q[b * Vn + tid] = 0.f; }

    // u = y @ Wv / asum -> bufB
    GEMM5(Wv, Cn, bufA, Cn, 0, Cn);
    if (ks == 0) {
#pragma unroll
        for (int v = 0; v < Vn; v++) {
            float ia = 1.0f / asum_s[v];
            ((float4*)&bufB[v * Cn])[cg] =
                make_float4(acc[v].x * ia, acc[v].y * ia, acc[v].z * ia, acc[v].w * ia);
        }
    }
    __syncthreads();

    // LN(u) with gu,bu -> bufA
    if (wid < Vn) {
        int v = wid;
        float s = 0.f, q = 0.f;
#pragma unroll
        for (int j = 0; j < 8; j++) {
            float x = bufB[v * Cn + lane + 32 * j];
            s += x; q = fmaf(x, x, q);
        }
#pragma unroll
        for (int o = 16; o; o >>= 1) {
            s += __shfl_xor_sync(0xFFFFFFFFu, s, o);
            q += __shfl_xor_sync(0xFFFFFFFFu, q, o);
        }
        float mean = s * (1.0f / Cn);
        float rs = rsqrtf(q * (1.0f / Cn) - mean * mean + LNEPS);
        if (lane == 0) { mrsh[v][0] = mean; mrsh[v][1] = rs; }
    }
    __syncthreads();
    for (int idx = tid; idx < Vn * Cn; idx += 512) {
        int v = idx >> 8, c = idx & 255;
        bufA[idx] = fmaf((bufB[idx] - mrsh[v][0]) * mrsh[v][1], gu[c], bu[c]);
    }
    __syncthreads();

    // hh = relu(h @ W1 + b1) -> bufB
#pragma unroll
    for (int h = 0; h < 2; h++) {
        GEMM5(W1, Cn, bufA, Cn, h * Cn, 2 * Cn);
        if (ks == 0) {
            float4 bb = ((const float4*)b1)[h * 64 + cg];
#pragma unroll
            for (int v = 0; v < Vn; v++) {
                ((float4*)&bufB[v * 2 * Cn + h * Cn])[cg] =
                    make_float4(fmaxf(acc[v].x + bb.x, 0.f), fmaxf(acc[v].y + bb.y, 0.f),
                                fmaxf(acc[v].z + bb.z, 0.f), fmaxf(acc[v].w + bb.w, 0.f));
            }
        }
    }
    __syncthreads();

    // d = hh @ W2 + b2; slots += d -> global, bufA
    GEMM5(W2, 2 * Cn, bufB, 2 * Cn, 0, Cn);
    if (ks == 0) {
        float4 bb = ((const float4*)b2)[cg];
#pragma unroll
        for (int v = 0; v < Vn; v++) {
            float4 sl = ((const float4*)g_slots)[((size_t)b * Vn + v) * 64 + cg];
            float4 ns = make_float4(sl.x + acc[v].x + bb.x, sl.y + acc[v].y + bb.y,
                                    sl.z + acc[v].z + bb.z, sl.w + acc[v].w + bb.w);
            ((float4*)g_slots)[((size_t)b * Vn + v) * 64 + cg] = ns;
            if (last) ((float4*)slots_out)[((size_t)b * Vn + v) * 64 + cg] = ns;
            ((float4*)&bufA[v * Cn])[cg] = ns;
        }
    }
    if (last) return;
    __syncthreads();

    // LN(slots) -> bufB; kq = · @ M -> g_kq
    if (wid < Vn) {
        int v = wid;
        float s = 0.f, q = 0.f;
#pragma unroll
        for (int j = 0; j < 8; j++) {
            float x = bufA[v * Cn + lane + 32 * j];
            s += x; q = fmaf(x, x, q);
        }
#pragma unroll
        for (int o = 16; o; o >>= 1) {
            s += __shfl_xor_sync(0xFFFFFFFFu, s, o);
            q += __shfl_xor_sync(0xFFFFFFFFu, q, o);
        }
        float mean = s * (1.0f / Cn);
        float rs = rsqrtf(q * (1.0f / Cn) - mean * mean + LNEPS);
        if (lane == 0) { mrsh[v][0] = mean; mrsh[v][1] = rs; }
    }
    __syncthreads();
    for (int idx = tid; idx < Vn * Cn; idx += 512) {
        int v = idx >> 8, c = idx & 255;
        bufB[idx] = fmaf((bufA[idx] - mrsh[v][0]) * mrsh[v][1], gs[c], bs[c]);
    }
    __syncthreads();
    GEMM5(g_M, Cn, bufB, Cn, 0, Cn);
    if (ks == 0) {
#pragma unroll
        for (int v = 0; v < Vn; v++)
            ((float4*)g_kq)[((size_t)b * Vn + v) * 64 + cg] = acc[v];
    }
}

// ------------------------------------------------------------------
extern "C" void kernel_launch(void* const* d_in, const int* in_sizes, int n_in,
                              void* d_out, int out_size) {
    (void)in_sizes; (void)n_in; (void)out_size;
    const float* feat  = (const float*)d_in[0];
    const float* noise = (const float*)d_in[1];
    const float* Wq    = (const float*)d_in[2];
    const float* Wk    = (const float*)d_in[3];
    const float* Wv    = (const float*)d_in[4];
    const float* scale = (const float*)d_in[5];
    const float* gin   = (const float*)d_in[6];
    const float* bin   = (const float*)d_in[7];
    const float* gs    = (const float*)d_in[8];
    const float* bs    = (const float*)d_in[9];
    const float* gu    = (const float*)d_in[10];
    const float* bu    = (const float*)d_in[11];
    const float* W1    = (const float*)d_in[12];
    const float* b1    = (const float*)d_in[13];
    const float* W2    = (const float*)d_in[14];
    const float* b2    = (const float*)d_in[15];
    const float* nsc   = (const float*)d_in[16];

    float* out = (float*)d_out;
    float* slots_out = out;                   // [B,V,C]
    float* attn_out = out + Bn * Vn * Cn;     // [B,L,V]

    base_stats<<<dim3(NCHUNK, Bn), 256>>>(feat);
    computeM_zero<<<Cn, Cn>>>(Wk, Wq, scale);
    init_prep<<<Bn * Vn, Cn>>>(noise, nsc, gs, bs);
    for (int t = 0; t < Tn; t++) {
        main_pass<<<dim3(Ln / 128, Bn), 256>>>(feat, gin, bin, attn_out, t == Tn - 1);
        chain2<<<Bn, 512>>>(Wv, gu, bu, W1, b1, W2, b2, gs, bs, gin, bin,
                            slots_out, t == Tn - 1);
    }
}